// round 16
// baseline (speedup 1.0000x reference)
#include <cuda_runtime.h>
#include <cuda_bf16.h>
#include <cstdint>

// ---------------- problem constants ----------------
#define N_NODES 32768
#define HID     256
#define N_GRAPH 256
#define NPG     128
#define NHEAD   8
#define HDIM    32
#define N_EDGE  524288
#define BIAS_ELEMS (N_GRAPH * NHEAD * NPG * NPG)   // 33,554,432 floats

// ---------------- scratch (no allocs allowed) ----------------
__device__ float g_Q[N_NODES * HID];
__device__ float g_K[N_NODES * HID];
__device__ float g_V[N_NODES * HID];
__device__ float g_A[N_NODES * HID];            // attention output before Wo
__device__ float g_biasS[BIAS_ELEMS];           // scatter layout [B][q][k][H]
__device__ float g_bias[BIAS_ELEMS];            // head-major  [B][H][q][k]

// =====================================================================
// tf32 helpers
// =====================================================================
__device__ __forceinline__ uint32_t f2tf(float x) {
    uint32_t r;
    asm("cvt.rna.tf32.f32 %0, %1;" : "=r"(r) : "f"(x));
    return r;
}

__device__ __forceinline__ void mma_tf32(float acc[4], const uint32_t a[4], const uint32_t b[2]) {
    asm volatile(
        "mma.sync.aligned.m16n8k8.row.col.f32.tf32.tf32.f32 "
        "{%0,%1,%2,%3}, {%4,%5,%6,%7}, {%8,%9}, {%0,%1,%2,%3};\n"
        : "+f"(acc[0]), "+f"(acc[1]), "+f"(acc[2]), "+f"(acc[3])
        : "r"(a[0]), "r"(a[1]), "r"(a[2]), "r"(a[3]), "r"(b[0]), "r"(b[1]));
}

// =====================================================================
// tf32 tensor-core GEMM (exact R10 structure: best measured config)
// CTA tile 128x64, BK=32, 8 warps (warp tile 32x32), m16n8k8 mma.
// =====================================================================
__global__ __launch_bounds__(256) void gemm_tf32_kernel(
    const float* __restrict__ A, const float* __restrict__ W,
    const float* __restrict__ bvec, float* __restrict__ C, float alpha)
{
    __shared__ uint32_t As[128][36];
    __shared__ uint32_t Bs[32][72];

    const int tid = threadIdx.x;
    const int lane = tid & 31, wid = tid >> 5;
    const int wm = (wid & 3) * 32, wn = (wid >> 2) * 32;
    const int g = lane >> 2, t = lane & 3;
    const int m0 = blockIdx.y * 128, n0 = blockIdx.x * 64;

    float acc[2][4][4] = {};

    for (int k0 = 0; k0 < 256; k0 += 32) {
#pragma unroll
        for (int i = 0; i < 4; i++) {
            int f = tid + i * 256;
            int row = f >> 3, cv = (f & 7) * 4;
            float4 v = *(const float4*)&A[(size_t)(m0 + row) * 256 + k0 + cv];
            uint4 u = make_uint4(f2tf(v.x), f2tf(v.y), f2tf(v.z), f2tf(v.w));
            *(uint4*)&As[row][cv] = u;
        }
#pragma unroll
        for (int i = 0; i < 2; i++) {
            int f = tid + i * 256;
            int row = f >> 4, cv = (f & 15) * 4;
            float4 v = *(const float4*)&W[(size_t)(k0 + row) * 256 + n0 + cv];
            uint4 u = make_uint4(f2tf(v.x), f2tf(v.y), f2tf(v.z), f2tf(v.w));
            *(uint4*)&Bs[row][cv] = u;
        }
        __syncthreads();

#pragma unroll
        for (int kk = 0; kk < 32; kk += 8) {
            uint32_t af[2][4], bf[4][2];
#pragma unroll
            for (int mt = 0; mt < 2; mt++) {
                int r = wm + mt * 16 + g;
                af[mt][0] = As[r][kk + t];
                af[mt][1] = As[r + 8][kk + t];
                af[mt][2] = As[r][kk + t + 4];
                af[mt][3] = As[r + 8][kk + t + 4];
            }
#pragma unroll
            for (int nt = 0; nt < 4; nt++) {
                int c = wn + nt * 8 + g;
                bf[nt][0] = Bs[kk + t][c];
                bf[nt][1] = Bs[kk + t + 4][c];
            }
#pragma unroll
            for (int mt = 0; mt < 2; mt++)
#pragma unroll
                for (int nt = 0; nt < 4; nt++)
                    mma_tf32(acc[mt][nt], af[mt], bf[nt]);
        }
        __syncthreads();
    }

#pragma unroll
    for (int mt = 0; mt < 2; mt++) {
#pragma unroll
        for (int nt = 0; nt < 4; nt++) {
            int col = n0 + wn + nt * 8 + 2 * t;
            float b0 = bvec[col], b1 = bvec[col + 1];
            int r = m0 + wm + mt * 16 + g;
            float2 o0 = make_float2(alpha * (acc[mt][nt][0] + b0), alpha * (acc[mt][nt][1] + b1));
            float2 o1 = make_float2(alpha * (acc[mt][nt][2] + b0), alpha * (acc[mt][nt][3] + b1));
            *(float2*)&C[(size_t)r * 256 + col] = o0;
            *(float2*)&C[(size_t)(r + 8) * 256 + col] = o1;
        }
    }
}

// Fused QKV variant: blockIdx.z selects projection (0=Q scaled, 1=K, 2=V)
__global__ __launch_bounds__(256) void gemm_tf32_qkv_kernel(
    const float* __restrict__ A,
    const float* __restrict__ Wq, const float* __restrict__ bq,
    const float* __restrict__ Wk, const float* __restrict__ bk,
    const float* __restrict__ Wv, const float* __restrict__ bv)
{
    __shared__ uint32_t As[128][36];
    __shared__ uint32_t Bs[32][72];

    const int z = blockIdx.z;
    const float* W    = (z == 0) ? Wq : (z == 1) ? Wk : Wv;
    const float* bvec = (z == 0) ? bq : (z == 1) ? bk : bv;
    float* C          = (z == 0) ? g_Q : (z == 1) ? g_K : g_V;
    const float alpha = (z == 0) ? 0.17677669529663689f : 1.0f;  // 1/sqrt(32) folded into Q

    const int tid = threadIdx.x;
    const int lane = tid & 31, wid = tid >> 5;
    const int wm = (wid & 3) * 32, wn = (wid >> 2) * 32;
    const int g = lane >> 2, t = lane & 3;
    const int m0 = blockIdx.y * 128, n0 = blockIdx.x * 64;

    float acc[2][4][4] = {};

    for (int k0 = 0; k0 < 256; k0 += 32) {
#pragma unroll
        for (int i = 0; i < 4; i++) {
            int f = tid + i * 256;
            int row = f >> 3, cv = (f & 7) * 4;
            float4 v = *(const float4*)&A[(size_t)(m0 + row) * 256 + k0 + cv];
            uint4 u = make_uint4(f2tf(v.x), f2tf(v.y), f2tf(v.z), f2tf(v.w));
            *(uint4*)&As[row][cv] = u;
        }
#pragma unroll
        for (int i = 0; i < 2; i++) {
            int f = tid + i * 256;
            int row = f >> 4, cv = (f & 15) * 4;
            float4 v = *(const float4*)&W[(size_t)(k0 + row) * 256 + n0 + cv];
            uint4 u = make_uint4(f2tf(v.x), f2tf(v.y), f2tf(v.z), f2tf(v.w));
            *(uint4*)&Bs[row][cv] = u;
        }
        __syncthreads();

#pragma unroll
        for (int kk = 0; kk < 32; kk += 8) {
            uint32_t af[2][4], bf[4][2];
#pragma unroll
            for (int mt = 0; mt < 2; mt++) {
                int r = wm + mt * 16 + g;
                af[mt][0] = As[r][kk + t];
                af[mt][1] = As[r + 8][kk + t];
                af[mt][2] = As[r][kk + t + 4];
                af[mt][3] = As[r + 8][kk + t + 4];
            }
#pragma unroll
            for (int nt = 0; nt < 4; nt++) {
                int c = wn + nt * 8 + g;
                bf[nt][0] = Bs[kk + t][c];
                bf[nt][1] = Bs[kk + t + 4][c];
            }
#pragma unroll
            for (int mt = 0; mt < 2; mt++)
#pragma unroll
                for (int nt = 0; nt < 4; nt++)
                    mma_tf32(acc[mt][nt], af[mt], bf[nt]);
        }
        __syncthreads();
    }

#pragma unroll
    for (int mt = 0; mt < 2; mt++) {
#pragma unroll
        for (int nt = 0; nt < 4; nt++) {
            int col = n0 + wn + nt * 8 + 2 * t;
            float b0 = bvec[col], b1 = bvec[col + 1];
            int r = m0 + wm + mt * 16 + g;
            float2 o0 = make_float2(alpha * (acc[mt][nt][0] + b0), alpha * (acc[mt][nt][1] + b1));
            float2 o1 = make_float2(alpha * (acc[mt][nt][2] + b0), alpha * (acc[mt][nt][3] + b1));
            *(float2*)&C[(size_t)r * 256 + col] = o0;
            *(float2*)&C[(size_t)(r + 8) * 256 + col] = o1;
        }
    }
}

// =====================================================================
// Zero the scatter buffer (graph replay must start clean each call)
// =====================================================================
__global__ void zero_bias_kernel()
{
    int i = blockIdx.x * blockDim.x + threadIdx.x;
    ((float4*)g_biasS)[i] = make_float4(0.f, 0.f, 0.f, 0.f);
}

// =====================================================================
// Edge bias scatter into [B][q][k][H] staging layout (vectorized atomics)
// =====================================================================
__device__ __forceinline__ void red_v4(float* p, float a, float b, float c, float d) {
    asm volatile("red.global.add.v4.f32 [%0], {%1,%2,%3,%4};"
                 :: "l"(p), "f"(a), "f"(b), "f"(c), "f"(d) : "memory");
}

__global__ __launch_bounds__(256) void edge_bias_kernel(
    const float* __restrict__ edge_attr, const int* __restrict__ edge_index,
    const int* __restrict__ gate_type, const float* __restrict__ gate_table,
    const float* __restrict__ We, const float* __restrict__ be)
{
    __shared__ float sGate[160];   // 20 x 8
    __shared__ float sWe[64];      // 8 x 8
    __shared__ float sBe[8];

    const int tid = threadIdx.x;
    if (tid < 160) sGate[tid] = gate_table[tid];
    if (tid < 64)  sWe[tid] = We[tid];
    if (tid < 8)   sBe[tid] = be[tid];
    __syncthreads();

    const int e = blockIdx.x * blockDim.x + tid;
    if (e >= N_EDGE) return;

    const int src = edge_index[e];
    const int dst = edge_index[N_EDGE + e];
    const int eb = src >> 7;          // NPG = 128
    const int sl = src & 127;
    const int dl = dst & 127;
    const int t = gate_type[e];

    float4 ea0 = *(const float4*)&edge_attr[(size_t)e * 8];
    float4 ea1 = *(const float4*)&edge_attr[(size_t)e * 8 + 4];
    float ea[8] = { ea0.x, ea0.y, ea0.z, ea0.w, ea1.x, ea1.y, ea1.z, ea1.w };

    float tot[8];
#pragma unroll
    for (int h = 0; h < 8; h++) {
        float s = sGate[t * 8 + h] + sBe[h];
#pragma unroll
        for (int f = 0; f < 8; f++) s += ea[f] * sWe[f * 8 + h];
        tot[h] = s;
    }

    float* pf = g_biasS + ((((size_t)eb * 128 + sl) * 128) + dl) * 8;
    red_v4(pf,     tot[0], tot[1], tot[2], tot[3]);
    red_v4(pf + 4, tot[4], tot[5], tot[6], tot[7]);

    if (sl != dl) {
        float* pr = g_biasS + ((((size_t)eb * 128 + dl) * 128) + sl) * 8;
        red_v4(pr,     tot[0], tot[1], tot[2], tot[3]);
        red_v4(pr + 4, tot[4], tot[5], tot[6], tot[7]);
    }
}

// =====================================================================
// Transpose bias: [B][q][k][H] -> [B][H][q][k]
// =====================================================================
__global__ __launch_bounds__(256) void transpose_bias_kernel()
{
    __shared__ float s[2][128][9];   // [row][k][h] padded
    const int t = threadIdx.x;
    const int r = t >> 7, j = t & 127;
    const int gq = blockIdx.x * 2 + r;

    const float4* in = (const float4*)(g_biasS + (size_t)gq * 1024);
#pragma unroll
    for (int i = 0; i < 2; i++) {
        int v = j + i * 128;               // float4 index 0..255
        float4 a = in[v];
        int k = v >> 1, h4 = (v & 1) * 4;
        s[r][k][h4 + 0] = a.x; s[r][k][h4 + 1] = a.y;
        s[r][k][h4 + 2] = a.z; s[r][k][h4 + 3] = a.w;
    }
    __syncthreads();

    const int b = gq >> 7, q = gq & 127;
    const int h = j >> 4, kc0 = j & 15;
    float4* outp = (float4*)(g_bias + (((size_t)(b * 8 + h) * 128 + q) * 128));
#pragma unroll
    for (int i = 0; i < 2; i++) {
        int kc = kc0 + i * 16;
        float4 o = make_float4(s[r][kc * 4 + 0][h], s[r][kc * 4 + 1][h],
                               s[r][kc * 4 + 2][h], s[r][kc * 4 + 3][h]);
        outp[kc] = o;
    }
}

// =====================================================================
// Tensor-core attention. CTA = (graph b, head h, q-half). 4 warps.
// smem: Q[64][36] + K[128][36] + P[64][132] tf32 = 61440 B -> 3 CTAs/SM
// =====================================================================
#define ATTN_SMEM_BYTES ((64 * 36 + 128 * 36 + 64 * 132) * 4)

__global__ __launch_bounds__(128, 3) void attn_mma_kernel()
{
    extern __shared__ uint32_t smx[];
    uint32_t* sQ = smx;                       // [64][36]
    uint32_t* sK = smx + 64 * 36;             // [128][36]
    uint32_t* sV = smx;                       // [128][36] (reuses sQ+sK after QK^T)
    uint32_t* sP = smx + 64 * 36 + 128 * 36;  // [64][132]

    const int bid = blockIdx.x;
    const int b  = bid >> 4;
    const int h  = (bid >> 1) & 7;
    const int q0 = (bid & 1) * 64;

    const int tid = threadIdx.x;
    const int lane = tid & 31, w = tid >> 5;
    const int g = lane >> 2, t = lane & 3;

    const float* Qg = g_Q + ((size_t)(b * NPG + q0)) * HID + h * HDIM;
    const float* Kg = g_K + ((size_t)b * NPG) * HID + h * HDIM;
    const float* Vg = g_V + ((size_t)b * NPG) * HID + h * HDIM;

    // ---- load Q (64x32) and K (128x32) as tf32 into smem ----
#pragma unroll
    for (int i = 0; i < 4; i++) {
        int f = tid + i * 128;
        int row = f >> 3, cv = (f & 7) * 4;
        float4 v = *(const float4*)&Qg[(size_t)row * HID + cv];
        uint4 u = make_uint4(f2tf(v.x), f2tf(v.y), f2tf(v.z), f2tf(v.w));
        *(uint4*)&sQ[row * 36 + cv] = u;
    }
#pragma unroll
    for (int i = 0; i < 8; i++) {
        int f = tid + i * 128;
        int row = f >> 3, cv = (f & 7) * 4;
        float4 v = *(const float4*)&Kg[(size_t)row * HID + cv];
        uint4 u = make_uint4(f2tf(v.x), f2tf(v.y), f2tf(v.z), f2tf(v.w));
        *(uint4*)&sK[row * 36 + cv] = u;
    }
    __syncthreads();

    const int r = w * 16 + g;   // this thread's base q-row (CTA-local)

    // ---- QK^T : S strip 16x128 per warp, in fragments ----
    uint32_t af[4][4];
#pragma unroll
    for (int ks = 0; ks < 4; ks++) {
        af[ks][0] = sQ[r * 36 + ks * 8 + t];
        af[ks][1] = sQ[(r + 8) * 36 + ks * 8 + t];
        af[ks][2] = sQ[r * 36 + ks * 8 + t + 4];
        af[ks][3] = sQ[(r + 8) * 36 + ks * 8 + t + 4];
    }

    float acc[16][4];
#pragma unroll
    for (int j = 0; j < 16; j++)
        acc[j][0] = acc[j][1] = acc[j][2] = acc[j][3] = 0.f;

#pragma unroll
    for (int j = 0; j < 16; j++) {
        int c = j * 8 + g;
#pragma unroll
        for (int ks = 0; ks < 4; ks++) {
            uint32_t bf[2];
            bf[0] = sK[c * 36 + ks * 8 + t];
            bf[1] = sK[c * 36 + ks * 8 + t + 4];
            mma_tf32(acc[j], af[ks], bf);
        }
    }

    // ---- add bias (head-major, coalesced float2 reads) ----
    const float* bg = g_bias + ((size_t)(b * NHEAD + h) * NPG + q0 + w * 16) * NPG;
#pragma unroll
    for (int j = 0; j < 16; j++) {
        float2 b0 = *(const float2*)&bg[g * NPG + j * 8 + 2 * t];
        float2 b1 = *(const float2*)&bg[(g + 8) * NPG + j * 8 + 2 * t];
        acc[j][0] += b0.x; acc[j][1] += b0.y;
        acc[j][2] += b1.x; acc[j][3] += b1.y;
    }

    // ---- softmax on fragments (rows g and g+8; 4 lanes per row) ----
    float m1 = -1e30f, m2 = -1e30f;
#pragma unroll
    for (int j = 0; j < 16; j++) {
        m1 = fmaxf(m1, fmaxf(acc[j][0], acc[j][1]));
        m2 = fmaxf(m2, fmaxf(acc[j][2], acc[j][3]));
    }
    m1 = fmaxf(m1, __shfl_xor_sync(0xffffffffu, m1, 1));
    m1 = fmaxf(m1, __shfl_xor_sync(0xffffffffu, m1, 2));
    m2 = fmaxf(m2, __shfl_xor_sync(0xffffffffu, m2, 1));
    m2 = fmaxf(m2, __shfl_xor_sync(0xffffffffu, m2, 2));

    float s1 = 0.f, s2 = 0.f;
#pragma unroll
    for (int j = 0; j < 16; j++) {
        acc[j][0] = __expf(acc[j][0] - m1);
        acc[j][1] = __expf(acc[j][1] - m1);
        acc[j][2] = __expf(acc[j][2] - m2);
        acc[j][3] = __expf(acc[j][3] - m2);
        s1 += acc[j][0] + acc[j][1];
        s2 += acc[j][2] + acc[j][3];
    }
    s1 += __shfl_xor_sync(0xffffffffu, s1, 1);
    s1 += __shfl_xor_sync(0xffffffffu, s1, 2);
    s2 += __shfl_xor_sync(0xffffffffu, s2, 1);
    s2 += __shfl_xor_sync(0xffffffffu, s2, 2);
    const float inv1 = 1.0f / s1, inv2 = 1.0f / s2;

    // ---- all warps done reading sQ/sK: repurpose that region for V ----
    __syncthreads();

    // P -> smem (tf32), warp-private strip
#pragma unroll
    for (int j = 0; j < 16; j++) {
        uint2 p0 = make_uint2(f2tf(acc[j][0] * inv1), f2tf(acc[j][1] * inv1));
        uint2 p1 = make_uint2(f2tf(acc[j][2] * inv2), f2tf(acc[j][3] * inv2));
        *(uint2*)&sP[r * 132 + j * 8 + 2 * t] = p0;
        *(uint2*)&sP[(r + 8) * 132 + j * 8 + 2 * t] = p1;
    }

    // V (128x32) -> smem as tf32 (overwrites sQ/sK region)
#pragma unroll
    for (int i = 0; i < 8; i++) {
        int f = tid + i * 128;
        int row = f >> 3, cv = (f & 7) * 4;
        float4 v = *(const float4*)&Vg[(size_t)row * HID + cv];
        uint4 u = make_uint4(f2tf(v.x), f2tf(v.y), f2tf(v.z), f2tf(v.w));
        *(uint4*)&sV[row * 36 + cv] = u;
    }
    __syncthreads();

    // ---- O = P @ V via mma (both operands from smem) ----
    float o[4][4] = {};
#pragma unroll
    for (int ks = 0; ks < 16; ks++) {
        uint32_t pf[4];
        pf[0] = sP[r * 132 + ks * 8 + t];
        pf[1] = sP[(r + 8) * 132 + ks * 8 + t];
        pf[2] = sP[r * 132 + ks * 8 + t + 4];
        pf[3] = sP[(r + 8) * 132 + ks * 8 + t + 4];
#pragma unroll
        for (int nt = 0; nt < 4; nt++) {
            uint32_t bf[2];
            bf[0] = sV[(ks * 8 + t) * 36 + nt * 8 + g];
            bf[1] = sV[(ks * 8 + t + 4) * 36 + nt * 8 + g];
            mma_tf32(o[nt], pf, bf);
        }
    }

    // ---- store O ----
    float* Og = g_A + ((size_t)(b * NPG + q0 + w * 16)) * HID + h * HDIM;
#pragma unroll
    for (int nt = 0; nt < 4; nt++) {
        int col = nt * 8 + 2 * t;
        *(float2*)&Og[(size_t)g * HID + col] = make_float2(o[nt][0], o[nt][1]);
        *(float2*)&Og[(size_t)(g + 8) * HID + col] = make_float2(o[nt][2], o[nt][3]);
    }
}

// =====================================================================
// launch: fork bias chain onto a side stream, overlap with QKV GEMM.
// Capture-legal fork/join via events; fresh handles per call (no device
// memory involved; kernel_launch is invoked only a handful of times).
// =====================================================================
extern "C" void kernel_launch(void* const* d_in, const int* in_sizes, int n_in,
                              void* d_out, int out_size)
{
    const float* x          = (const float*)d_in[0];
    const float* edge_attr  = (const float*)d_in[1];
    const float* Wq         = (const float*)d_in[2];
    const float* bq         = (const float*)d_in[3];
    const float* Wk         = (const float*)d_in[4];
    const float* bk         = (const float*)d_in[5];
    const float* Wv         = (const float*)d_in[6];
    const float* bv         = (const float*)d_in[7];
    const float* Wo         = (const float*)d_in[8];
    const float* bo         = (const float*)d_in[9];
    const float* gate_table = (const float*)d_in[10];
    const float* We         = (const float*)d_in[11];
    const float* be         = (const float*)d_in[12];
    const int*   edge_index = (const int*)d_in[13];
    const int*   gate_type  = (const int*)d_in[14];
    float*       out        = (float*)d_out;

    float* Ap;
    cudaGetSymbolAddress((void**)&Ap, g_A);

    cudaFuncSetAttribute(attn_mma_kernel, cudaFuncAttributeMaxDynamicSharedMemorySize,
                         ATTN_SMEM_BYTES);

    cudaStream_t s2;
    cudaEvent_t evFork, evJoin;
    cudaStreamCreateWithFlags(&s2, cudaStreamNonBlocking);
    cudaEventCreateWithFlags(&evFork, cudaEventDisableTiming);
    cudaEventCreateWithFlags(&evJoin, cudaEventDisableTiming);

    // fork side stream off the main (capture) stream
    cudaEventRecord(evFork, 0);
    cudaStreamWaitEvent(s2, evFork, 0);

    // --- side stream: bias chain (zero -> scatter -> transpose) ---
    zero_bias_kernel<<<BIAS_ELEMS / 4 / 256, 256, 0, s2>>>();
    edge_bias_kernel<<<N_EDGE / 256, 256, 0, s2>>>(edge_attr, edge_index, gate_type,
                                                   gate_table, We, be);
    transpose_bias_kernel<<<N_GRAPH * NPG / 2, 256, 0, s2>>>();
    cudaEventRecord(evJoin, s2);

    // --- main stream: QKV projections (overlaps with bias chain) ---
    dim3 gqkv(HID / 64, N_NODES / 128, 3);   // (4, 256, 3)
    gemm_tf32_qkv_kernel<<<gqkv, 256>>>(x, Wq, bq, Wk, bk, Wv, bv);

    // join: attention needs both QKV and the bias tensor
    cudaStreamWaitEvent(0, evJoin, 0);

    attn_mma_kernel<<<N_GRAPH * NHEAD * 2, 128, ATTN_SMEM_BYTES>>>();

    dim3 go(HID / 64, N_NODES / 128);        // (4, 256)
    gemm_tf32_kernel<<<go, 256>>>(Ap, Wo, bo, out, 1.0f);
}

// round 17
// speedup vs baseline: 1.4396x; 1.4396x over previous
#include <cuda_runtime.h>
#include <cuda_bf16.h>
#include <cstdint>

// ---------------- problem constants ----------------
#define N_NODES 32768
#define HID     256
#define N_GRAPH 256
#define NPG     128
#define NHEAD   8
#define HDIM    32
#define N_EDGE  524288
#define BIAS_ELEMS (N_GRAPH * NHEAD * NPG * NPG)   // 33,554,432 floats

// ---------------- scratch (no allocs allowed) ----------------
__device__ uint32_t g_Xc[N_NODES * HID];        // x pre-converted to tf32
__device__ uint32_t g_Wc[4 * HID * HID];        // Wq,Wk,Wv,Wo tf32 (concatenated)
__device__ uint32_t g_Qc[N_NODES * HID];        // Q tf32 (scale folded)
__device__ uint32_t g_Kc[N_NODES * HID];        // K tf32
__device__ uint32_t g_Vc[N_NODES * HID];        // V tf32
__device__ uint32_t g_Ac[N_NODES * HID];        // attn output tf32 (input to Wo)
__device__ float g_biasS[BIAS_ELEMS];           // scatter layout [B][q][k][H]
__device__ float g_bias[BIAS_ELEMS];            // head-major  [B][H][q][k]

// =====================================================================
// tf32 helpers
// =====================================================================
__device__ __forceinline__ uint32_t f2tf(float x) {
    uint32_t r;
    asm("cvt.rna.tf32.f32 %0, %1;" : "=r"(r) : "f"(x));
    return r;
}

__device__ __forceinline__ void mma_tf32(float acc[4], const uint32_t a[4], const uint32_t b[2]) {
    asm volatile(
        "mma.sync.aligned.m16n8k8.row.col.f32.tf32.tf32.f32 "
        "{%0,%1,%2,%3}, {%4,%5,%6,%7}, {%8,%9}, {%0,%1,%2,%3};\n"
        : "+f"(acc[0]), "+f"(acc[1]), "+f"(acc[2]), "+f"(acc[3])
        : "r"(a[0]), "r"(a[1]), "r"(a[2]), "r"(a[3]), "r"(b[0]), "r"(b[1]));
}

__device__ __forceinline__ void cp16(uint32_t* dst_smem, const uint32_t* src_gmem) {
    uint32_t s = (uint32_t)__cvta_generic_to_shared(dst_smem);
    asm volatile("cp.async.cg.shared.global [%0], [%1], 16;" :: "r"(s), "l"(src_gmem) : "memory");
}

// =====================================================================
// Pre-conversion kernels (fp32 -> tf32, rna — identical rounding to R10's
// in-GEMM conversion, just hoisted out of the hot loop)
// =====================================================================
__global__ __launch_bounds__(256) void conv_x_kernel(const float* __restrict__ x)
{
    size_t i = ((size_t)blockIdx.x * 256 + threadIdx.x) * 4;
    float4 v = *(const float4*)&x[i];
    uint4 u = make_uint4(f2tf(v.x), f2tf(v.y), f2tf(v.z), f2tf(v.w));
    *(uint4*)&g_Xc[i] = u;
}

__global__ __launch_bounds__(256) void conv_w_kernel(
    const float* __restrict__ Wq, const float* __restrict__ Wk,
    const float* __restrict__ Wv, const float* __restrict__ Wo)
{
    const int z = blockIdx.y;
    const float* W = (z == 0) ? Wq : (z == 1) ? Wk : (z == 2) ? Wv : Wo;
    int i = (blockIdx.x * 256 + threadIdx.x) * 4;   // 64 blocks x 256 thr x 4 = 65536
    float4 v = *(const float4*)&W[i];
    uint4 u = make_uint4(f2tf(v.x), f2tf(v.y), f2tf(v.z), f2tf(v.w));
    *(uint4*)&g_Wc[(size_t)z * HID * HID + i] = u;
}

// =====================================================================
// tf32 tensor-core GEMM, cp.async double-buffered fill.
// Mainloop fragment loads / mma schedule / epilogue layout = R10 (validated).
// CTA tile 128x64, BK=32, 8 warps (warp tile 32x32), m16n8k8 mma.
// smem: 2 stages x (As 128x36 + Bs 32x72) = 55296 B dynamic -> 4 CTAs/SM.
// =====================================================================
#define GEMM_STAGE_WORDS (128 * 36 + 32 * 72)          // 6912
#define GEMM_SMEM_BYTES  (2 * GEMM_STAGE_WORDS * 4)    // 55296

__device__ __forceinline__ void gemm_issue(
    const uint32_t* __restrict__ A, const uint32_t* __restrict__ W,
    int m0, int n0, int j, uint32_t* As, uint32_t* Bs, int tid)
{
#pragma unroll
    for (int i = 0; i < 4; i++) {
        int f = tid + i * 256, row = f >> 3, cv = (f & 7) * 4;
        cp16(As + row * 36 + cv, A + (size_t)(m0 + row) * 256 + j * 32 + cv);
    }
#pragma unroll
    for (int i = 0; i < 2; i++) {
        int f = tid + i * 256, row = f >> 4, cv = (f & 15) * 4;
        cp16(Bs + row * 72 + cv, W + (size_t)(j * 32 + row) * 256 + n0 + cv);
    }
    asm volatile("cp.async.commit_group;" ::: "memory");
}

template<bool TF32OUT>
__device__ __forceinline__ void gemm_async_body(
    const uint32_t* __restrict__ A, const uint32_t* __restrict__ W,
    const float* __restrict__ bvec, void* __restrict__ Cptr, float alpha,
    int m0, int n0, uint32_t* dsm)
{
    const int tid = threadIdx.x;
    const int lane = tid & 31, wid = tid >> 5;
    const int wm = (wid & 3) * 32, wn = (wid >> 2) * 32;
    const int g = lane >> 2, t = lane & 3;

    float acc[2][4][4] = {};

    gemm_issue(A, W, m0, n0, 0, dsm, dsm + 128 * 36, tid);

    for (int j = 0; j < 8; j++) {
        const int buf = j & 1;
        uint32_t* As = dsm + buf * GEMM_STAGE_WORDS;
        uint32_t* Bs = As + 128 * 36;

        if (j < 7) {
            uint32_t* As2 = dsm + (buf ^ 1) * GEMM_STAGE_WORDS;
            gemm_issue(A, W, m0, n0, j + 1, As2, As2 + 128 * 36, tid);
            asm volatile("cp.async.wait_group 1;" ::: "memory");
        } else {
            asm volatile("cp.async.wait_group 0;" ::: "memory");
        }
        __syncthreads();

#pragma unroll
        for (int kk = 0; kk < 32; kk += 8) {
            uint32_t af[2][4], bf[4][2];
#pragma unroll
            for (int mt = 0; mt < 2; mt++) {
                int r = wm + mt * 16 + g;
                af[mt][0] = As[r * 36 + kk + t];
                af[mt][1] = As[(r + 8) * 36 + kk + t];
                af[mt][2] = As[r * 36 + kk + t + 4];
                af[mt][3] = As[(r + 8) * 36 + kk + t + 4];
            }
#pragma unroll
            for (int nt = 0; nt < 4; nt++) {
                int c = wn + nt * 8 + g;
                bf[nt][0] = Bs[(kk + t) * 72 + c];
                bf[nt][1] = Bs[(kk + t + 4) * 72 + c];
            }
#pragma unroll
            for (int mt = 0; mt < 2; mt++)
#pragma unroll
                for (int nt = 0; nt < 4; nt++)
                    mma_tf32(acc[mt][nt], af[mt], bf[nt]);
        }
        __syncthreads();   // all warps done with this buffer before its refill next iter
    }

    // ---- epilogue (fragment layout unchanged from R10) ----
#pragma unroll
    for (int mt = 0; mt < 2; mt++) {
#pragma unroll
        for (int nt = 0; nt < 4; nt++) {
            int col = n0 + wn + nt * 8 + 2 * t;
            float b0 = bvec[col], b1 = bvec[col + 1];
            int r = m0 + wm + mt * 16 + g;
            float v00 = alpha * (acc[mt][nt][0] + b0);
            float v01 = alpha * (acc[mt][nt][1] + b1);
            float v10 = alpha * (acc[mt][nt][2] + b0);
            float v11 = alpha * (acc[mt][nt][3] + b1);
            if (TF32OUT) {
                uint32_t* C = (uint32_t*)Cptr;
                *(uint2*)&C[(size_t)r * 256 + col] = make_uint2(f2tf(v00), f2tf(v01));
                *(uint2*)&C[(size_t)(r + 8) * 256 + col] = make_uint2(f2tf(v10), f2tf(v11));
            } else {
                float* C = (float*)Cptr;
                *(float2*)&C[(size_t)r * 256 + col] = make_float2(v00, v01);
                *(float2*)&C[(size_t)(r + 8) * 256 + col] = make_float2(v10, v11);
            }
        }
    }
}

// Fused QKV: blockIdx.z selects projection (0=Q scaled, 1=K, 2=V); outputs tf32
__global__ __launch_bounds__(256) void gemm_qkv_kernel(
    const float* __restrict__ bq, const float* __restrict__ bk,
    const float* __restrict__ bv)
{
    extern __shared__ uint32_t dsm[];
    const int z = blockIdx.z;
    const float* bvec = (z == 0) ? bq : (z == 1) ? bk : bv;
    uint32_t* C       = (z == 0) ? g_Qc : (z == 1) ? g_Kc : g_Vc;
    const float alpha = (z == 0) ? 0.17677669529663689f : 1.0f;   // 1/sqrt(32) in Q

    gemm_async_body<true>(g_Xc, g_Wc + (size_t)z * HID * HID, bvec, C, alpha,
                          blockIdx.y * 128, blockIdx.x * 64, dsm);
}

// Wo projection: reads tf32 g_Ac, writes fp32 result
__global__ __launch_bounds__(256) void gemm_wo_kernel(
    const float* __restrict__ bo, float* __restrict__ out)
{
    extern __shared__ uint32_t dsm[];
    gemm_async_body<false>(g_Ac, g_Wc + (size_t)3 * HID * HID, bo, out, 1.0f,
                           blockIdx.y * 128, blockIdx.x * 64, dsm);
}

// =====================================================================
// Zero the scatter buffer (graph replay must start clean each call)
// =====================================================================
__global__ void zero_bias_kernel()
{
    int i = blockIdx.x * blockDim.x + threadIdx.x;
    ((float4*)g_biasS)[i] = make_float4(0.f, 0.f, 0.f, 0.f);
}

// =====================================================================
// Edge bias scatter into [B][q][k][H] staging layout (vectorized atomics)
// =====================================================================
__device__ __forceinline__ void red_v4(float* p, float a, float b, float c, float d) {
    asm volatile("red.global.add.v4.f32 [%0], {%1,%2,%3,%4};"
                 :: "l"(p), "f"(a), "f"(b), "f"(c), "f"(d) : "memory");
}

__global__ __launch_bounds__(256) void edge_bias_kernel(
    const float* __restrict__ edge_attr, const int* __restrict__ edge_index,
    const int* __restrict__ gate_type, const float* __restrict__ gate_table,
    const float* __restrict__ We, const float* __restrict__ be)
{
    __shared__ float sGate[160];   // 20 x 8
    __shared__ float sWe[64];      // 8 x 8
    __shared__ float sBe[8];

    const int tid = threadIdx.x;
    if (tid < 160) sGate[tid] = gate_table[tid];
    if (tid < 64)  sWe[tid] = We[tid];
    if (tid < 8)   sBe[tid] = be[tid];
    __syncthreads();

    const int e = blockIdx.x * blockDim.x + tid;
    if (e >= N_EDGE) return;

    const int src = edge_index[e];
    const int dst = edge_index[N_EDGE + e];
    const int eb = src >> 7;          // NPG = 128
    const int sl = src & 127;
    const int dl = dst & 127;
    const int t = gate_type[e];

    float4 ea0 = *(const float4*)&edge_attr[(size_t)e * 8];
    float4 ea1 = *(const float4*)&edge_attr[(size_t)e * 8 + 4];
    float ea[8] = { ea0.x, ea0.y, ea0.z, ea0.w, ea1.x, ea1.y, ea1.z, ea1.w };

    float tot[8];
#pragma unroll
    for (int h = 0; h < 8; h++) {
        float s = sGate[t * 8 + h] + sBe[h];
#pragma unroll
        for (int f = 0; f < 8; f++) s += ea[f] * sWe[f * 8 + h];
        tot[h] = s;
    }

    float* pf = g_biasS + ((((size_t)eb * 128 + sl) * 128) + dl) * 8;
    red_v4(pf,     tot[0], tot[1], tot[2], tot[3]);
    red_v4(pf + 4, tot[4], tot[5], tot[6], tot[7]);

    if (sl != dl) {
        float* pr = g_biasS + ((((size_t)eb * 128 + dl) * 128) + sl) * 8;
        red_v4(pr,     tot[0], tot[1], tot[2], tot[3]);
        red_v4(pr + 4, tot[4], tot[5], tot[6], tot[7]);
    }
}

// =====================================================================
// Transpose bias: [B][q][k][H] -> [B][H][q][k]
// =====================================================================
__global__ __launch_bounds__(256) void transpose_bias_kernel()
{
    __shared__ float s[2][128][9];   // [row][k][h] padded
    const int t = threadIdx.x;
    const int r = t >> 7, j = t & 127;
    const int gq = blockIdx.x * 2 + r;

    const float4* in = (const float4*)(g_biasS + (size_t)gq * 1024);
#pragma unroll
    for (int i = 0; i < 2; i++) {
        int v = j + i * 128;               // float4 index 0..255
        float4 a = in[v];
        int k = v >> 1, h4 = (v & 1) * 4;
        s[r][k][h4 + 0] = a.x; s[r][k][h4 + 1] = a.y;
        s[r][k][h4 + 2] = a.z; s[r][k][h4 + 3] = a.w;
    }
    __syncthreads();

    const int b = gq >> 7, q = gq & 127;
    const int h = j >> 4, kc0 = j & 15;
    float4* outp = (float4*)(g_bias + (((size_t)(b * 8 + h) * 128 + q) * 128));
#pragma unroll
    for (int i = 0; i < 2; i++) {
        int kc = kc0 + i * 16;
        float4 o = make_float4(s[r][kc * 4 + 0][h], s[r][kc * 4 + 1][h],
                               s[r][kc * 4 + 2][h], s[r][kc * 4 + 3][h]);
        outp[kc] = o;
    }
}

// =====================================================================
// Tensor-core attention (R10 structure). CTA = (graph b, head h, q-half).
// Q/K/V arrive pre-converted tf32 -> plain uint4 copies into smem.
// Output stored as tf32 into g_Ac (consumed by Wo GEMM).
// smem: Q[64][36] + K[128][36] + P[64][132] = 61440 B -> 3 CTAs/SM
// =====================================================================
#define ATTN_SMEM_BYTES ((64 * 36 + 128 * 36 + 64 * 132) * 4)

__global__ __launch_bounds__(128, 3) void attn_mma_kernel()
{
    extern __shared__ uint32_t smx[];
    uint32_t* sQ = smx;                       // [64][36]
    uint32_t* sK = smx + 64 * 36;             // [128][36]
    uint32_t* sV = smx;                       // [128][36] (reuses sQ+sK after QK^T)
    uint32_t* sP = smx + 64 * 36 + 128 * 36;  // [64][132]

    const int bid = blockIdx.x;
    const int b  = bid >> 4;
    const int h  = (bid >> 1) & 7;
    const int q0 = (bid & 1) * 64;

    const int tid = threadIdx.x;
    const int lane = tid & 31, w = tid >> 5;
    const int g = lane >> 2, t = lane & 3;

    const uint32_t* Qg = g_Qc + ((size_t)(b * NPG + q0)) * HID + h * HDIM;
    const uint32_t* Kg = g_Kc + ((size_t)b * NPG) * HID + h * HDIM;
    const uint32_t* Vg = g_Vc + ((size_t)b * NPG) * HID + h * HDIM;

    // ---- load Q (64x32) and K (128x32) tf32 into smem (straight copies) ----
#pragma unroll
    for (int i = 0; i < 4; i++) {
        int f = tid + i * 128;
        int row = f >> 3, cv = (f & 7) * 4;
        *(uint4*)&sQ[row * 36 + cv] = *(const uint4*)&Qg[(size_t)row * HID + cv];
    }
#pragma unroll
    for (int i = 0; i < 8; i++) {
        int f = tid + i * 128;
        int row = f >> 3, cv = (f & 7) * 4;
        *(uint4*)&sK[row * 36 + cv] = *(const uint4*)&Kg[(size_t)row * HID + cv];
    }
    __syncthreads();

    const int r = w * 16 + g;   // this thread's base q-row (CTA-local)

    // ---- QK^T : S strip 16x128 per warp, in fragments ----
    uint32_t af[4][4];
#pragma unroll
    for (int ks = 0; ks < 4; ks++) {
        af[ks][0] = sQ[r * 36 + ks * 8 + t];
        af[ks][1] = sQ[(r + 8) * 36 + ks * 8 + t];
        af[ks][2] = sQ[r * 36 + ks * 8 + t + 4];
        af[ks][3] = sQ[(r + 8) * 36 + ks * 8 + t + 4];
    }

    float acc[16][4];
#pragma unroll
    for (int j = 0; j < 16; j++)
        acc[j][0] = acc[j][1] = acc[j][2] = acc[j][3] = 0.f;

#pragma unroll
    for (int j = 0; j < 16; j++) {
        int c = j * 8 + g;
#pragma unroll
        for (int ks = 0; ks < 4; ks++) {
            uint32_t bf[2];
            bf[0] = sK[c * 36 + ks * 8 + t];
            bf[1] = sK[c * 36 + ks * 8 + t + 4];
            mma_tf32(acc[j], af[ks], bf);
        }
    }

    // ---- add bias (head-major, coalesced float2 reads) ----
    const float* bg = g_bias + ((size_t)(b * NHEAD + h) * NPG + q0 + w * 16) * NPG;
#pragma unroll
    for (int j = 0; j < 16; j++) {
        float2 b0 = *(const float2*)&bg[g * NPG + j * 8 + 2 * t];
        float2 b1 = *(const float2*)&bg[(g + 8) * NPG + j * 8 + 2 * t];
        acc[j][0] += b0.x; acc[j][1] += b0.y;
        acc[j][2] += b1.x; acc[j][3] += b1.y;
    }

    // ---- softmax on fragments (rows r and r+8; 4 lanes per row) ----
    float m1 = -1e30f, m2 = -1e30f;
#pragma unroll
    for (int j = 0; j < 16; j++) {
        m1 = fmaxf(m1, fmaxf(acc[j][0], acc[j][1]));
        m2 = fmaxf(m2, fmaxf(acc[j][2], acc[j][3]));
    }
    m1 = fmaxf(m1, __shfl_xor_sync(0xffffffffu, m1, 1));
    m1 = fmaxf(m1, __shfl_xor_sync(0xffffffffu, m1, 2));
    m2 = fmaxf(m2, __shfl_xor_sync(0xffffffffu, m2, 1));
    m2 = fmaxf(m2, __shfl_xor_sync(0xffffffffu, m2, 2));

    float s1 = 0.f, s2 = 0.f;
#pragma unroll
    for (int j = 0; j < 16; j++) {
        acc[j][0] = __expf(acc[j][0] - m1);
        acc[j][1] = __expf(acc[j][1] - m1);
        acc[j][2] = __expf(acc[j][2] - m2);
        acc[j][3] = __expf(acc[j][3] - m2);
        s1 += acc[j][0] + acc[j][1];
        s2 += acc[j][2] + acc[j][3];
    }
    s1 += __shfl_xor_sync(0xffffffffu, s1, 1);
    s1 += __shfl_xor_sync(0xffffffffu, s1, 2);
    s2 += __shfl_xor_sync(0xffffffffu, s2, 1);
    s2 += __shfl_xor_sync(0xffffffffu, s2, 2);
    const float inv1 = 1.0f / s1, inv2 = 1.0f / s2;

    // ---- all warps done reading sQ/sK: repurpose that region for V ----
    __syncthreads();

    // P -> smem (tf32), warp-private strip
#pragma unroll
    for (int j = 0; j < 16; j++) {
        uint2 p0 = make_uint2(f2tf(acc[j][0] * inv1), f2tf(acc[j][1] * inv1));
        uint2 p1 = make_uint2(f2tf(acc[j][2] * inv2), f2tf(acc[j][3] * inv2));
        *(uint2*)&sP[r * 132 + j * 8 + 2 * t] = p0;
        *(uint2*)&sP[(r + 8) * 132 + j * 8 + 2 * t] = p1;
    }

    // V (128x32 tf32) -> smem (overwrites sQ/sK region)
#pragma unroll
    for (int i = 0; i < 8; i++) {
        int f = tid + i * 128;
        int row = f >> 3, cv = (f & 7) * 4;
        *(uint4*)&sV[row * 36 + cv] = *(const uint4*)&Vg[(size_t)row * HID + cv];
    }
    __syncthreads();

    // ---- O = P @ V via mma (both operands from smem) ----
    float o[4][4] = {};
#pragma unroll
    for (int ks = 0; ks < 16; ks++) {
        uint32_t pf[4];
        pf[0] = sP[r * 132 + ks * 8 + t];
        pf[1] = sP[(r + 8) * 132 + ks * 8 + t];
        pf[2] = sP[r * 132 + ks * 8 + t + 4];
        pf[3] = sP[(r + 8) * 132 + ks * 8 + t + 4];
#pragma unroll
        for (int nt = 0; nt < 4; nt++) {
            uint32_t bf[2];
            bf[0] = sV[(ks * 8 + t) * 36 + nt * 8 + g];
            bf[1] = sV[(ks * 8 + t + 4) * 36 + nt * 8 + g];
            mma_tf32(o[nt], pf, bf);
        }
    }

    // ---- store O as tf32 into g_Ac (Wo GEMM consumes pre-converted) ----
    uint32_t* Og = g_Ac + ((size_t)(b * NPG + q0 + w * 16)) * HID + h * HDIM;
#pragma unroll
    for (int nt = 0; nt < 4; nt++) {
        int col = nt * 8 + 2 * t;
        *(uint2*)&Og[(size_t)g * HID + col] = make_uint2(f2tf(o[nt][0]), f2tf(o[nt][1]));
        *(uint2*)&Og[(size_t)(g + 8) * HID + col] = make_uint2(f2tf(o[nt][2]), f2tf(o[nt][3]));
    }
}

// =====================================================================
// launch — strictly serial (R16 showed overlap only causes contention)
// =====================================================================
extern "C" void kernel_launch(void* const* d_in, const int* in_sizes, int n_in,
                              void* d_out, int out_size)
{
    const float* x          = (const float*)d_in[0];
    const float* edge_attr  = (const float*)d_in[1];
    const float* Wq         = (const float*)d_in[2];
    const float* bq         = (const float*)d_in[3];
    const float* Wk         = (const float*)d_in[4];
    const float* bk         = (const float*)d_in[5];
    const float* Wv         = (const float*)d_in[6];
    const float* bv         = (const float*)d_in[7];
    const float* Wo         = (const float*)d_in[8];
    const float* bo         = (const float*)d_in[9];
    const float* gate_table = (const float*)d_in[10];
    const float* We         = (const float*)d_in[11];
    const float* be         = (const float*)d_in[12];
    const int*   edge_index = (const int*)d_in[13];
    const int*   gate_type  = (const int*)d_in[14];
    float*       out        = (float*)d_out;

    cudaFuncSetAttribute(attn_mma_kernel, cudaFuncAttributeMaxDynamicSharedMemorySize,
                         ATTN_SMEM_BYTES);
    cudaFuncSetAttribute(gemm_qkv_kernel, cudaFuncAttributeMaxDynamicSharedMemorySize,
                         GEMM_SMEM_BYTES);
    cudaFuncSetAttribute(gemm_wo_kernel, cudaFuncAttributeMaxDynamicSharedMemorySize,
                         GEMM_SMEM_BYTES);

    // pre-convert x and weights to tf32
    conv_x_kernel<<<N_NODES * HID / 4 / 256, 256>>>(x);
    dim3 gw(HID * HID / 4 / 256, 4);         // (64, 4)
    conv_w_kernel<<<gw, 256>>>(Wq, Wk, Wv, Wo);

    // bias chain: zero -> vectorized scatter -> transpose to head-major
    zero_bias_kernel<<<BIAS_ELEMS / 4 / 256, 256>>>();
    edge_bias_kernel<<<N_EDGE / 256, 256>>>(edge_attr, edge_index, gate_type,
                                            gate_table, We, be);
    transpose_bias_kernel<<<N_GRAPH * NPG / 2, 256>>>();

    // QKV projections (cp.async double-buffered)
    dim3 gqkv(HID / 64, N_NODES / 128, 3);   // (4, 256, 3)
    gemm_qkv_kernel<<<gqkv, 256, GEMM_SMEM_BYTES>>>(bq, bk, bv);

    attn_mma_kernel<<<N_GRAPH * NHEAD * 2, 128, ATTN_SMEM_BYTES>>>();

    // output projection
    dim3 go(HID / 64, N_NODES / 128);        // (4, 256)
    gemm_wo_kernel<<<go, 256, GEMM_SMEM_BYTES>>>(bo, out);
}